// round 6
// baseline (speedup 1.0000x reference)
#include <cuda_runtime.h>
#include <cstdint>
#include <cstddef>

// ---------------------------------------------------------------------------
// Rel_Transformer_Layer: N=2048, D=1024, H=8, DK=128, L=4, FF=4096
// Round 5: 3-stage cp.async B + double-buffered A-frag (1 sync/iter),
// deterministic split-K for small-grid GEMMs (AV, Wo, FFN2).
// ---------------------------------------------------------------------------

#define NTOK 2048
#define DMOD 1024
#define HEADS 8
#define DKH 128
#define FFD 4096
#define SCALE 0.08838834764831845f  // 1/sqrt(128)

// -------------------- scratch (static device allocations) ------------------
__device__ float g_x2[NTOK * DMOD];
__device__ float g_bias2d[(size_t)NTOK * NTOK];
__device__ float g_Wqkv[3 * DMOD * DMOD];
__device__ float g_bqkv[3 * DMOD];
__device__ float g_qkv[3 * NTOK * DMOD];
__device__ float g_S[(size_t)HEADS * NTOK * NTOK];   // 128 MB
__device__ float g_ao[NTOK * DMOD];
__device__ float g_t[NTOK * DMOD];
__device__ float g_h1[NTOK * DMOD];
__device__ float g_ff[(size_t)NTOK * FFD];
__device__ float g_part[(size_t)8 * 4 * 256 * 1024]; // 32 MB split-K partials
__device__ float g_etw[64];

// -------------------- helpers ----------------------------------------------
__device__ __forceinline__ uint32_t f2tf(float f) {
    uint32_t u;
    asm("cvt.rna.tf32.f32 %0, %1;" : "=r"(u) : "f"(f));
    return u;
}
__device__ __forceinline__ void cpasync16(uint32_t smem_addr, const void* gsrc) {
    asm volatile("cp.async.cg.shared.global [%0], [%1], 16;"
                 :: "r"(smem_addr), "l"(gsrc));
}

// -------------------- batched tf32-MMA GEMM with split-K --------------------
// z = batch*nsplit + split. C[z] = A[batch][:, split*Keff:(split+1)*Keff] @
//                                  B[batch][rows split*Keff..] (+epilogue)
// BM=BN=128, BK=32, 256 threads (8 warps 2x4), warp tile 64x32 of m16n8k8.
#define BM 128
#define BN 128
#define BK 32
#define BPITCH 136
#define AFW1 4096                    // one A fragment buffer (16KB)
#define BBW (32 * BPITCH)            // one B buffer (4352 words)
#define GSMEM_BYTES ((2 * AFW1 + 3 * BBW) * 4)   // 84992

__device__ __forceinline__ void storeA_frag(
    uint32_t* AFb, const float4 stA[2][2], int wmS, int iS, int g, int tg)
{
#pragma unroll
    for (int h = 0; h < 2; h++) {
        const int ks4h = (tg >> 1) + 2 * h;
        const int hk = tg & 1;
#pragma unroll
        for (int cc = 0; cc < 4; cc++) {
            const int lane_sw = (g * 4 + cc) ^ (g & 3);
            const int word =
                (((wmS * 4 + ks4h) * 4 + iS) * 32 + lane_sw) * 4 + 2 * hk;
            uint32_t v0 = f2tf(((const float*)&stA[0][h])[cc]);
            uint32_t v1 = f2tf(((const float*)&stA[1][h])[cc]);
            *(uint2*)&AFb[word] = make_uint2(v0, v1);
        }
    }
}

__global__ __launch_bounds__(256, 2) void tgemm_bat(
    const float* __restrict__ A, const float* __restrict__ B,
    const float* __restrict__ biasvec, const float* __restrict__ attnB,
    float* __restrict__ C, int M, int N, int K,
    size_t sA, size_t sB, size_t sC, size_t sBias,
    float scale, int doRelu, int nsplit)
{
    extern __shared__ uint32_t sm[];
    uint32_t* AF = sm;                 // 2 * AFW1
    uint32_t* BBuf = sm + 2 * AFW1;    // 3 * BBW

    const int tid = threadIdx.x;
    const int wid = tid >> 5;
    const int lane = tid & 31;
    const int g = lane >> 2;
    const int tg = lane & 3;
    const int wm = wid >> 2;
    const int wn = wid & 3;

    const int batch = blockIdx.z / nsplit;
    const int split = blockIdx.z - batch * nsplit;
    const int Keff = K / nsplit;
    const int nIter = Keff / BK;

    const float* Ab = A + (size_t)batch * sA + (size_t)split * Keff
                        + (size_t)blockIdx.y * BM * K;
    const float* Bb = B + (size_t)batch * sB + (size_t)split * Keff * N
                        + (size_t)blockIdx.x * BN;
    float* Cb = C + (size_t)blockIdx.z * sC;
    const float* bvv = biasvec ? biasvec + (size_t)batch * sBias : nullptr;

    // A fill mapping: warp wid fills rows [wid*16, wid*16+16)
    const int wmS = wid >> 2;
    const int iS = wid & 3;
    const float* Ag0 = Ab + (size_t)(wid * 16 + g) * K + tg * 4;
    const float* Ag1 = Ag0 + (size_t)8 * K;

    // B fill mapping
    const int bRow = tid >> 5;
    const int bCol = (tid & 31) << 2;
    const float* Bg = Bb + (size_t)bRow * N + bCol;
    const uint32_t bShared = (uint32_t)__cvta_generic_to_shared(BBuf);

    float4 stA[2][2];
    // ---- prologue: tile0 -> AF[0], cp.async B0,B1; stage A tile1 ----
    stA[0][0] = *(const float4*)(Ag0);
    stA[0][1] = *(const float4*)(Ag0 + 16);
    stA[1][0] = *(const float4*)(Ag1);
    stA[1][1] = *(const float4*)(Ag1 + 16);
    storeA_frag(AF, stA, wmS, iS, g, tg);
#pragma unroll
    for (int rh = 0; rh < 32; rh += 8)
        cpasync16(bShared + (((bRow + rh) * BPITCH + bCol) << 2),
                  Bg + (size_t)rh * N);
    asm volatile("cp.async.commit_group;");
    stA[0][0] = *(const float4*)(Ag0 + BK);
    stA[0][1] = *(const float4*)(Ag0 + BK + 16);
    stA[1][0] = *(const float4*)(Ag1 + BK);
    stA[1][1] = *(const float4*)(Ag1 + BK + 16);
    {
        const float* Bn = Bg + (size_t)BK * N;
        const uint32_t db = bShared + (BBW << 2);
#pragma unroll
        for (int rh = 0; rh < 32; rh += 8)
            cpasync16(db + (((bRow + rh) * BPITCH + bCol) << 2),
                      Bn + (size_t)rh * N);
    }
    asm volatile("cp.async.commit_group;");

    float acc[4][4][4];
#pragma unroll
    for (int i = 0; i < 4; i++)
#pragma unroll
        for (int j = 0; j < 4; j++)
#pragma unroll
            for (int r = 0; r < 4; r++) acc[i][j][r] = 0.f;

    for (int it = 0; it < nIter; it++) {
        asm volatile("cp.async.wait_group 1;");
        __syncthreads();

        // prefetch B(it+2) into buf (it+2)%3 (safe: last read in iter it-1)
        if (it + 2 < nIter) {
            const float* Bn = Bg + (size_t)(it + 2) * BK * N;
            const uint32_t db = bShared + (((it + 2) % 3) * BBW << 2);
#pragma unroll
            for (int rh = 0; rh < 32; rh += 8)
                cpasync16(db + (((bRow + rh) * BPITCH + bCol) << 2),
                          Bn + (size_t)rh * N);
        }
        asm volatile("cp.async.commit_group;");

        // store staged A(it+1) into AF[(it+1)&1]; stage A(it+2)
        if (it + 1 < nIter)
            storeA_frag(AF + ((it + 1) & 1) * AFW1, stA, wmS, iS, g, tg);
        if (it + 2 < nIter) {
            const float* An0 = Ag0 + (size_t)(it + 2) * BK;
            const float* An1 = Ag1 + (size_t)(it + 2) * BK;
            stA[0][0] = *(const float4*)(An0);
            stA[0][1] = *(const float4*)(An0 + 16);
            stA[1][0] = *(const float4*)(An1);
            stA[1][1] = *(const float4*)(An1 + 16);
        }

        // compute tile it
        const uint32_t* AFr = AF + (it & 1) * AFW1;
        const uint32_t* Bs = BBuf + (it % 3) * BBW;
#pragma unroll
        for (int ks4 = 0; ks4 < 4; ks4++) {
            uint32_t af[4][4];
            uint32_t bf[4][2];
#pragma unroll
            for (int i = 0; i < 4; i++) {
                const uint4 q = *(const uint4*)
                    &AFr[(((wm * 4 + ks4) * 4 + i) * 32 + (lane ^ (g & 3))) * 4];
                af[i][0] = q.x; af[i][1] = q.y; af[i][2] = q.z; af[i][3] = q.w;
            }
            const int kl = ks4 * 8 + tg;
#pragma unroll
            for (int j = 0; j < 4; j++) {
                const int c0 = wn * 32 + j * 8 + g;
                bf[j][0] = Bs[kl * BPITCH + c0];
                bf[j][1] = Bs[(kl + 4) * BPITCH + c0];
            }
#pragma unroll
            for (int i = 0; i < 4; i++)
#pragma unroll
                for (int j = 0; j < 4; j++) {
                    asm volatile(
                        "mma.sync.aligned.m16n8k8.row.col.f32.tf32.tf32.f32 "
                        "{%0,%1,%2,%3}, {%4,%5,%6,%7}, {%8,%9}, {%0,%1,%2,%3};"
                        : "+f"(acc[i][j][0]), "+f"(acc[i][j][1]),
                          "+f"(acc[i][j][2]), "+f"(acc[i][j][3])
                        : "r"(af[i][0]), "r"(af[i][1]), "r"(af[i][2]),
                          "r"(af[i][3]), "r"(bf[j][0]), "r"(bf[j][1]));
                }
        }
        __syncthreads();
    }

    // epilogue
#pragma unroll
    for (int i = 0; i < 4; i++) {
        const int row = blockIdx.y * BM + wm * 64 + i * 16 + g;
#pragma unroll
        for (int j = 0; j < 4; j++) {
            const int col = blockIdx.x * BN + wn * 32 + j * 8 + 2 * tg;
            float v0 = acc[i][j][0] * scale;
            float v1 = acc[i][j][1] * scale;
            float v2 = acc[i][j][2] * scale;
            float v3 = acc[i][j][3] * scale;
            if (bvv) {
                v0 += bvv[col];     v1 += bvv[col + 1];
                v2 += bvv[col];     v3 += bvv[col + 1];
            }
            if (attnB) {
                const float2 t0 = *(const float2*)(attnB + (size_t)row * N + col);
                const float2 t1 = *(const float2*)(attnB + (size_t)(row + 8) * N + col);
                v0 += t0.x; v1 += t0.y; v2 += t1.x; v3 += t1.y;
            }
            if (doRelu) {
                v0 = fmaxf(v0, 0.f); v1 = fmaxf(v1, 0.f);
                v2 = fmaxf(v2, 0.f); v3 = fmaxf(v3, 0.f);
            }
            *(float2*)(Cb + (size_t)row * N + col) = make_float2(v0, v1);
            *(float2*)(Cb + (size_t)(row + 8) * N + col) = make_float2(v2, v3);
        }
    }
}

// -------------------- split-K reduce: out = sum_s part (+bias) -------------
__global__ void reduceK_k(const float4* __restrict__ part,
                          float4* __restrict__ outp,
                          const float* __restrict__ bias,
                          int nsplit, size_t MN4, int N4)
{
    const size_t i = (size_t)blockIdx.x * blockDim.x + threadIdx.x;
    const size_t b = i / MN4;
    const size_t e = i - b * MN4;
    const float4* p = part + b * (size_t)nsplit * MN4 + e;
    float4 a = p[0];
    for (int s = 1; s < nsplit; s++) {
        const float4 v = p[(size_t)s * MN4];
        a.x += v.x; a.y += v.y; a.z += v.z; a.w += v.w;
    }
    if (bias) {
        const float4 bb = ((const float4*)bias)[e % N4];
        a.x += bb.x; a.y += bb.y; a.z += bb.z; a.w += bb.w;
    }
    outp[i] = a;
}

// -------------------- x2 = x + in_deg_emb[deg] + out_deg_emb[deg] ----------
__global__ void addemb_k(const float* __restrict__ x,
                         const int* __restrict__ ind,
                         const int* __restrict__ outd,
                         const float* __restrict__ ie,
                         const float* __restrict__ oe,
                         float* __restrict__ x2)
{
    const int n = blockIdx.x;
    const int di = ind[n];
    const int dd = outd[n];
    const float4* xr = (const float4*)(x + (size_t)n * DMOD);
    const float4* ir = (const float4*)(ie + (size_t)di * DMOD);
    const float4* orr = (const float4*)(oe + (size_t)dd * DMOD);
    float4* yr = (float4*)(x2 + (size_t)n * DMOD);
    const int i = threadIdx.x;
    float4 a = xr[i], b = ir[i], c = orr[i];
    a.x += b.x + c.x; a.y += b.y + c.y; a.z += b.z + c.z; a.w += b.w + c.w;
    yr[i] = a;
}

// -------------------- etw[r] = scale * dot(rel_emb[r], rel_weight[r]) ------
__global__ void etw_k(const float* __restrict__ re,
                      const float* __restrict__ rw,
                      float* __restrict__ etw)
{
    const int t = threadIdx.x;
    float s = 0.f;
    for (int j = 0; j < DKH; j++) s += re[t * DKH + j] * rw[t * DKH + j];
    etw[t] = s * SCALE;
}

// ---- bias2d[n,m] = path_len_emb[dist] + sum_l etw[pet[l]]*paw[l] ----------
__global__ void bias2d_k(const int* __restrict__ dist,
                         const int4* __restrict__ pet,
                         const float4* __restrict__ paw,
                         const float* __restrict__ plen,
                         const float* __restrict__ etw,
                         float* __restrict__ out)
{
    const size_t i = (size_t)blockIdx.x * blockDim.x + threadIdx.x;
    const int4 e = pet[i];
    const float4 w = paw[i];
    float b = plen[dist[i]];
    b += etw[e.x] * w.x + etw[e.y] * w.y + etw[e.z] * w.z + etw[e.w] * w.w;
    out[i] = b;
}

// -------------------- single-pass row softmax ------------------------------
__global__ void softmax_k(float* __restrict__ S)
{
    const size_t r = (size_t)blockIdx.y * NTOK + blockIdx.x;
    float* row = S + r * NTOK;
    const int t = threadIdx.x;
    __shared__ float red[8];

    float4 v0 = *(const float4*)(row + t * 8);
    float4 v1 = *(const float4*)(row + t * 8 + 4);

    float m = fmaxf(fmaxf(fmaxf(v0.x, v0.y), fmaxf(v0.z, v0.w)),
                    fmaxf(fmaxf(v1.x, v1.y), fmaxf(v1.z, v1.w)));
#pragma unroll
    for (int s = 16; s > 0; s >>= 1)
        m = fmaxf(m, __shfl_xor_sync(0xffffffffu, m, s));
    if ((t & 31) == 0) red[t >> 5] = m;
    __syncthreads();
    if (t < 8) {
        float mm = red[t];
#pragma unroll
        for (int s = 4; s > 0; s >>= 1)
            mm = fmaxf(mm, __shfl_xor_sync(0xffu, mm, s));
        red[t] = mm;
    }
    __syncthreads();
    m = red[0];

    v0.x = __expf(v0.x - m); v0.y = __expf(v0.y - m);
    v0.z = __expf(v0.z - m); v0.w = __expf(v0.w - m);
    v1.x = __expf(v1.x - m); v1.y = __expf(v1.y - m);
    v1.z = __expf(v1.z - m); v1.w = __expf(v1.w - m);
    float sum = v0.x + v0.y + v0.z + v0.w + v1.x + v1.y + v1.z + v1.w;
#pragma unroll
    for (int s = 16; s > 0; s >>= 1)
        sum += __shfl_xor_sync(0xffffffffu, sum, s);
    __syncthreads();
    if ((t & 31) == 0) red[t >> 5] = sum;
    __syncthreads();
    if (t < 8) {
        float ss = red[t];
#pragma unroll
        for (int s = 4; s > 0; s >>= 1)
            ss += __shfl_xor_sync(0xffu, ss, s);
        red[t] = ss;
    }
    __syncthreads();
    const float inv = 1.f / red[0];

    v0.x *= inv; v0.y *= inv; v0.z *= inv; v0.w *= inv;
    v1.x *= inv; v1.y *= inv; v1.z *= inv; v1.w *= inv;
    *(float4*)(row + t * 8) = v0;
    *(float4*)(row + t * 8 + 4) = v1;
}

// -------------------- y = LayerNorm(a + c) * g + b -------------------------
__global__ void add_ln_k(const float* __restrict__ a,
                         const float* __restrict__ c,
                         const float* __restrict__ g,
                         const float* __restrict__ b,
                         float* __restrict__ y)
{
    const int n = blockIdx.x;
    const float* ar = a + (size_t)n * DMOD;
    const float* cr = c + (size_t)n * DMOD;
    float* yr = y + (size_t)n * DMOD;
    __shared__ float r1[256], r2[256];

    float s = 0.f, s2 = 0.f;
    for (int i = threadIdx.x; i < DMOD; i += 256) {
        float v = ar[i] + cr[i];
        s += v;
        s2 += v * v;
    }
    r1[threadIdx.x] = s;
    r2[threadIdx.x] = s2;
    __syncthreads();
    for (int st = 128; st > 0; st >>= 1) {
        if (threadIdx.x < st) {
            r1[threadIdx.x] += r1[threadIdx.x + st];
            r2[threadIdx.x] += r2[threadIdx.x + st];
        }
        __syncthreads();
    }
    const float mean = r1[0] * (1.f / DMOD);
    const float var = r2[0] * (1.f / DMOD) - mean * mean;
    const float rstd = rsqrtf(var + 1e-5f);
    for (int i = threadIdx.x; i < DMOD; i += 256) {
        float v = ar[i] + cr[i];
        yr[i] = (v - mean) * rstd * g[i] + b[i];
    }
}

// ---------------------------------------------------------------------------
extern "C" void kernel_launch(void* const* d_in, const int* in_sizes, int n_in,
                              void* d_out, int out_size)
{
    const float* x      = (const float*)d_in[0];
    const float* lgx    = (const float*)d_in[1];
    const int* in_deg   = (const int*)d_in[2];
    const int* out_deg  = (const int*)d_in[3];
    const int* dist     = (const int*)d_in[4];
    const int* pet      = (const int*)d_in[5];
    const float* paw    = (const float*)d_in[6];
    const float* rel_e  = (const float*)d_in[7];
    const float* rel_w  = (const float*)d_in[8];
    const float* ide    = (const float*)d_in[9];
    const float* ode    = (const float*)d_in[10];
    const float* plen   = (const float*)d_in[11];
    const float* Wq = (const float*)d_in[12];  const float* bq = (const float*)d_in[13];
    const float* Wk = (const float*)d_in[14];  const float* bk = (const float*)d_in[15];
    const float* Wv = (const float*)d_in[16];  const float* bv = (const float*)d_in[17];
    const float* Wo = (const float*)d_in[18];  const float* bo = (const float*)d_in[19];
    const float* ln1g = (const float*)d_in[20]; const float* ln1b = (const float*)d_in[21];
    const float* W1 = (const float*)d_in[22];  const float* b1 = (const float*)d_in[23];
    const float* W2 = (const float*)d_in[24];  const float* b2 = (const float*)d_in[25];
    const float* ln2g = (const float*)d_in[26]; const float* ln2b = (const float*)d_in[27];

    float* out = (float*)d_out;

    float *x2, *bias2d, *Wqkv, *bqkv, *qkv, *S, *ao, *t, *h1, *ff, *part, *etw;
    cudaGetSymbolAddress((void**)&x2, g_x2);
    cudaGetSymbolAddress((void**)&bias2d, g_bias2d);
    cudaGetSymbolAddress((void**)&Wqkv, g_Wqkv);
    cudaGetSymbolAddress((void**)&bqkv, g_bqkv);
    cudaGetSymbolAddress((void**)&qkv, g_qkv);
    cudaGetSymbolAddress((void**)&S, g_S);
    cudaGetSymbolAddress((void**)&ao, g_ao);
    cudaGetSymbolAddress((void**)&t, g_t);
    cudaGetSymbolAddress((void**)&h1, g_h1);
    cudaGetSymbolAddress((void**)&ff, g_ff);
    cudaGetSymbolAddress((void**)&part, g_part);
    cudaGetSymbolAddress((void**)&etw, g_etw);

    cudaFuncSetAttribute(tgemm_bat,
                         cudaFuncAttributeMaxDynamicSharedMemorySize,
                         GSMEM_BYTES);

    const size_t WB = (size_t)DMOD * DMOD * sizeof(float);

    // lgx passthrough: second output component
    cudaMemcpyAsync(out + (size_t)NTOK * DMOD, lgx,
                    (size_t)NTOK * 8 * DMOD * sizeof(float),
                    cudaMemcpyDeviceToDevice);

    // pack Wq/Wk/Wv (+biases) contiguously for the batched projection
    cudaMemcpyAsync(Wqkv,            Wq, WB, cudaMemcpyDeviceToDevice);
    cudaMemcpyAsync(Wqkv + WB / 4,   Wk, WB, cudaMemcpyDeviceToDevice);
    cudaMemcpyAsync(Wqkv + WB / 2,   Wv, WB, cudaMemcpyDeviceToDevice);
    cudaMemcpyAsync(bqkv,            bq, DMOD * sizeof(float), cudaMemcpyDeviceToDevice);
    cudaMemcpyAsync(bqkv + DMOD,     bk, DMOD * sizeof(float), cudaMemcpyDeviceToDevice);
    cudaMemcpyAsync(bqkv + 2 * DMOD, bv, DMOD * sizeof(float), cudaMemcpyDeviceToDevice);

    // structural node bias
    addemb_k<<<NTOK, 256>>>(x, in_deg, out_deg, ide, ode, x2);

    // attention bias matrix [N, N]
    etw_k<<<1, 64>>>(rel_e, rel_w, etw);
    bias2d_k<<<(NTOK * NTOK) / 256, 256>>>(dist, (const int4*)pet,
                                           (const float4*)paw, plen, etw,
                                           bias2d);

    const size_t ND = (size_t)NTOK * DMOD;
    const size_t HSTR = (size_t)256 * DMOD;      // per-head stride (=2048*128)
    const size_t SSTR = (size_t)NTOK * NTOK;
    float* q = qkv;
    float* k = qkv + ND;
    float* v = qkv + 2 * ND;

    // Q/K/V projections batched
    tgemm_bat<<<dim3(DMOD / BN, NTOK / BM, 3), 256, GSMEM_BYTES>>>(
        x2, Wqkv, bqkv, nullptr, qkv, NTOK, DMOD, DMOD,
        0, (size_t)DMOD * DMOD, ND, DMOD, 1.f, 0, 1);

    // QK^T batched over heads, epilogue: *scale + bias2d
    tgemm_bat<<<dim3(NTOK / BN, NTOK / BM, HEADS), 256, GSMEM_BYTES>>>(
        q, k, nullptr, bias2d, S, NTOK, NTOK, DKH,
        HSTR, HSTR, SSTR, 0, SCALE, 0, 1);

    // softmax over all heads' rows
    softmax_k<<<dim3(NTOK, HEADS), 256>>>(S);

    // attn @ V batched over heads, split-K=4 -> partials, then reduce
    tgemm_bat<<<dim3(1, NTOK / BM, HEADS * 4), 256, GSMEM_BYTES>>>(
        S, v, nullptr, nullptr, part, NTOK, DKH, NTOK,
        SSTR, HSTR, (size_t)NTOK * DKH, 0, 1.f, 0, 4);
    reduceK_k<<<(HEADS * NTOK * DKH / 4) / 256, 256>>>(
        (const float4*)part, (float4*)ao, nullptr, 4,
        (size_t)NTOK * DKH / 4, DKH / 4);

    // output projection split-K=2 + reduce(+bo), residual + LN1
    tgemm_bat<<<dim3(DMOD / BN, NTOK / BM, 2), 256, GSMEM_BYTES>>>(
        ao, Wo, nullptr, nullptr, part, NTOK, DMOD, DMOD,
        0, 0, ND, 0, 1.f, 0, 2);
    reduceK_k<<<(NTOK * DMOD / 4) / 256, 256>>>(
        (const float4*)part, (float4*)t, bo, 2, ND / 4, DMOD / 4);
    add_ln_k<<<NTOK, 256>>>(x2, t, ln1g, ln1b, h1);

    // FFN1 + relu
    tgemm_bat<<<dim3(FFD / BN, NTOK / BM, 1), 256, GSMEM_BYTES>>>(
        h1, W1, b1, nullptr, ff, NTOK, FFD, DMOD,
        0, 0, 0, FFD, 1.f, 1, 1);
    // FFN2 split-K=2 + reduce(+b2), residual + LN2
    tgemm_bat<<<dim3(DMOD / BN, NTOK / BM, 2), 256, GSMEM_BYTES>>>(
        ff, W2, nullptr, nullptr, part, NTOK, DMOD, FFD,
        0, 0, ND, 0, 1.f, 0, 2);
    reduceK_k<<<(NTOK * DMOD / 4) / 256, 256>>>(
        (const float4*)part, (float4*)t, b2, 2, ND / 4, DMOD / 4);
    add_ln_k<<<NTOK, 256>>>(h1, t, ln2g, ln2b, out);
}

// round 8
// speedup vs baseline: 1.0814x; 1.0814x over previous
#include <cuda_runtime.h>
#include <cstdint>
#include <cstddef>

// ---------------------------------------------------------------------------
// Rel_Transformer_Layer: N=2048, D=1024, H=8, DK=128, L=4, FF=4096
// Round 8: flash-fused attention (QK + bias + online softmax + PV in one
// kernel, S never materialized). Weight GEMMs keep the verified tf32 HMMA
// pipeline (tcgen05 unavailable in this toolchain: ptxas targets sm_103).
// ---------------------------------------------------------------------------

#define NTOK 2048
#define DMOD 1024
#define HEADS 8
#define DKH 128
#define FFD 4096
#define SCALE 0.08838834764831845f  // 1/sqrt(128)

// -------------------- scratch (static device allocations) ------------------
__device__ float g_x2[NTOK * DMOD];
__device__ float g_bias2d[(size_t)NTOK * NTOK];
__device__ float g_Wqkv[3 * DMOD * DMOD];
__device__ float g_bqkv[3 * DMOD];
__device__ float g_qkv[3 * NTOK * DMOD];
__device__ float g_ao[NTOK * DMOD];
__device__ float g_t[NTOK * DMOD];
__device__ float g_h1[NTOK * DMOD];
__device__ float g_ff[(size_t)NTOK * FFD];
__device__ float g_part[(size_t)8 * 4 * 256 * 1024];
__device__ float g_etw[64];

// -------------------- helpers ----------------------------------------------
__device__ __forceinline__ uint32_t f2tf(float f) {
    uint32_t u; asm("cvt.rna.tf32.f32 %0, %1;" : "=r"(u) : "f"(f)); return u;
}
__device__ __forceinline__ void cpasync16(uint32_t s, const void* g) {
    asm volatile("cp.async.cg.shared.global [%0], [%1], 16;" :: "r"(s), "l"(g));
}
#define COMMIT() asm volatile("cp.async.commit_group;" ::: "memory")
#define WAITG1() asm volatile("cp.async.wait_group 1;" ::: "memory")

#define BM 128
#define BN 128
#define BK 32
#define BPITCH 136
#define AFW1 4096
#define BBW (32 * BPITCH)
#define GSMEM_BYTES ((2 * AFW1 + 3 * BBW) * 4)

__device__ __forceinline__ void storeA_frag(
    uint32_t* AFb, const float4 stA[2][2], int wmS, int iS, int g, int tg)
{
#pragma unroll
    for (int h = 0; h < 2; h++) {
        const int ks4h = (tg >> 1) + 2 * h;
        const int hk = tg & 1;
#pragma unroll
        for (int cc = 0; cc < 4; cc++) {
            const int lane_sw = (g * 4 + cc) ^ (g & 3);
            const int word = (((wmS * 4 + ks4h) * 4 + iS) * 32 + lane_sw) * 4 + 2 * hk;
            uint32_t v0 = f2tf(((const float*)&stA[0][h])[cc]);
            uint32_t v1 = f2tf(((const float*)&stA[1][h])[cc]);
            *(uint2*)&AFb[word] = make_uint2(v0, v1);
        }
    }
}

#define MMA_TF32(acc, af, bf)                                              \
    asm volatile(                                                          \
        "mma.sync.aligned.m16n8k8.row.col.f32.tf32.tf32.f32 "              \
        "{%0,%1,%2,%3}, {%4,%5,%6,%7}, {%8,%9}, {%0,%1,%2,%3};"            \
        : "+f"(acc[0]), "+f"(acc[1]), "+f"(acc[2]), "+f"(acc[3])           \
        : "r"(af[0]), "r"(af[1]), "r"(af[2]), "r"(af[3]),                  \
          "r"(bf[0]), "r"(bf[1]))

// ==================== flash attention ====================
// Per (head z, row-block y of 128): O = softmax(Q Kt * s + bias) V.
// smem (words): AFQ[16384] | BBuf[3*4352] | Ps[128*132] | redM[512] | redS[512]
#define PSP 132
#define FL_BBUF 16384
#define FL_PS   29440
#define FL_REDM 46336
#define FLASH_SMEM (47360 * 4)

__global__ __launch_bounds__(256, 1) void flash_k(
    const float* __restrict__ Q, const float* __restrict__ Km,
    const float* __restrict__ V, const float* __restrict__ bias2d,
    float* __restrict__ O)
{
    extern __shared__ uint32_t sm[];
    uint32_t* AFQ = sm;
    uint32_t* BBuf = sm + FL_BBUF;
    uint32_t* Ps = sm + FL_PS;
    float* redM = (float*)(sm + FL_REDM);
    float* redS = redM + 512;

    const int tid = threadIdx.x, wid = tid >> 5, lane = tid & 31;
    const int g = lane >> 2, tg = lane & 3, wm = wid >> 2, wn = wid & 3;
    const int h = blockIdx.z, by = blockIdx.y;
    const size_t HB = (size_t)h * 256 * DMOD;

    const float* Qh = Q + HB;    // [2048][128]
    const float* Kh = Km + HB;   // [128][2048]
    const float* Vh = V + HB;    // [2048][128]

    // ---- cp.async chunk streamer: q = tile*8 + phase (ph<4: K, else V) ----
    const int bRow = tid >> 5, bCol = (tid & 31) << 2;
    const uint32_t bSh = (uint32_t)__cvta_generic_to_shared(BBuf);
    auto issue_body = [&](int qq) {
        const int t = qq >> 3, ph = qq & 7;
        const float* src;
        int stride;
        if (ph < 4) { src = Kh + (size_t)(ph * 32 + bRow) * NTOK + t * 128 + bCol; stride = NTOK; }
        else        { src = Vh + (size_t)(t * 128 + (ph - 4) * 32 + bRow) * DKH + bCol; stride = DKH; }
        const uint32_t db = bSh + ((qq % 3) * BBW << 2);
#pragma unroll
        for (int rh = 0; rh < 32; rh += 8)
            cpasync16(db + (((bRow + rh) * BPITCH + bCol) << 2), src + (size_t)rh * stride);
    };
    issue_body(0); COMMIT();
    issue_body(1); COMMIT();

    // ---- stage Q fragments (all K=128 -> 4 chunks, written once) ----
    {
        const int wmS = wid >> 2, iS = wid & 3;
        const float* Qg0 = Qh + (size_t)(by * 128 + wid * 16 + g) * DKH + tg * 4;
        const float* Qg1 = Qg0 + 8 * DKH;
#pragma unroll
        for (int c = 0; c < 4; c++) {
            float4 stA[2][2];
            stA[0][0] = *(const float4*)(Qg0 + c * 32);
            stA[0][1] = *(const float4*)(Qg0 + c * 32 + 16);
            stA[1][0] = *(const float4*)(Qg1 + c * 32);
            stA[1][1] = *(const float4*)(Qg1 + c * 32 + 16);
            storeA_frag(AFQ + c * 4096, stA, wmS, iS, g, tg);
        }
    }

    float m8[8], l8[8], oacc[4][4][4];
#pragma unroll
    for (int s = 0; s < 8; s++) { m8[s] = -1e30f; l8[s] = 0.f; }
#pragma unroll
    for (int i = 0; i < 4; i++)
#pragma unroll
        for (int j = 0; j < 4; j++)
#pragma unroll
            for (int r = 0; r < 4; r++) oacc[i][j][r] = 0.f;

    int q = 0;
    for (int t = 0; t < 16; t++) {
        float sacc[4][4][4];
#pragma unroll
        for (int i = 0; i < 4; i++)
#pragma unroll
            for (int j = 0; j < 4; j++)
#pragma unroll
                for (int r = 0; r < 4; r++) sacc[i][j][r] = 0.f;

        // ---- S = Q @ K tile (4 dk-chunks) ----
        for (int c = 0; c < 4; c++, q++) {
            WAITG1();
            __syncthreads();
            if (q + 2 < 128) issue_body(q + 2);
            COMMIT();
            const uint32_t* AFr = AFQ + c * 4096;
            const uint32_t* Bs = BBuf + (q % 3) * BBW;
#pragma unroll
            for (int ks4 = 0; ks4 < 4; ks4++) {
                uint32_t af[4][4], bf[4][2];
#pragma unroll
                for (int i = 0; i < 4; i++) {
                    const uint4 qd = *(const uint4*)
                        &AFr[(((wm * 4 + ks4) * 4 + i) * 32 + (lane ^ (g & 3))) * 4];
                    af[i][0] = qd.x; af[i][1] = qd.y; af[i][2] = qd.z; af[i][3] = qd.w;
                }
                const int kl = ks4 * 8 + tg;
#pragma unroll
                for (int j = 0; j < 4; j++) {
                    const int c0 = wn * 32 + j * 8 + g;
                    bf[j][0] = Bs[kl * BPITCH + c0];
                    bf[j][1] = Bs[(kl + 4) * BPITCH + c0];
                }
#pragma unroll
                for (int i = 0; i < 4; i++)
#pragma unroll
                    for (int j = 0; j < 4; j++) MMA_TF32(sacc[i][j], af[i], bf[j]);
            }
            __syncthreads();
        }

        // ---- scale + bias ----
#pragma unroll
        for (int i = 0; i < 4; i++) {
            const int rg = by * 128 + wm * 64 + i * 16 + g;
#pragma unroll
            for (int j = 0; j < 4; j++) {
                const int cg = t * 128 + wn * 32 + j * 8 + 2 * tg;
                const float2 b0 = *(const float2*)(bias2d + (size_t)rg * NTOK + cg);
                const float2 b1 = *(const float2*)(bias2d + (size_t)(rg + 8) * NTOK + cg);
                sacc[i][j][0] = sacc[i][j][0] * SCALE + b0.x;
                sacc[i][j][1] = sacc[i][j][1] * SCALE + b0.y;
                sacc[i][j][2] = sacc[i][j][2] * SCALE + b1.x;
                sacc[i][j][3] = sacc[i][j][3] * SCALE + b1.y;
            }
        }

        // ---- online softmax: tile row max ----
        float pm[8];
#pragma unroll
        for (int i = 0; i < 4; i++)
#pragma unroll
            for (int h2 = 0; h2 < 2; h2++) {
                float v = -1e30f;
#pragma unroll
                for (int j = 0; j < 4; j++)
                    v = fmaxf(v, fmaxf(sacc[i][j][2 * h2], sacc[i][j][2 * h2 + 1]));
                pm[i * 2 + h2] = v;
            }
#pragma unroll
        for (int s = 0; s < 8; s++) {
            pm[s] = fmaxf(pm[s], __shfl_xor_sync(~0u, pm[s], 1));
            pm[s] = fmaxf(pm[s], __shfl_xor_sync(~0u, pm[s], 2));
        }
#pragma unroll
        for (int s = 0; s < 8; s++) {
            const int row = wm * 64 + (s >> 1) * 16 + (s & 1) * 8 + g;
            if (tg == 0) redM[row * 4 + wn] = pm[s];
        }
        __syncthreads();

        float alpha[8], nm[8];
#pragma unroll
        for (int s = 0; s < 8; s++) {
            const int row = wm * 64 + (s >> 1) * 16 + (s & 1) * 8 + g;
            float tm = fmaxf(fmaxf(redM[row * 4], redM[row * 4 + 1]),
                             fmaxf(redM[row * 4 + 2], redM[row * 4 + 3]));
            nm[s] = fmaxf(m8[s], tm);
            alpha[s] = __expf(m8[s] - nm[s]);
            m8[s] = nm[s];
        }

        // ---- P = exp(S - m), partial sums, store P to smem ----
        float ps[8];
#pragma unroll
        for (int s = 0; s < 8; s++) ps[s] = 0.f;
#pragma unroll
        for (int i = 0; i < 4; i++)
#pragma unroll
            for (int h2 = 0; h2 < 2; h2++) {
                const int row = wm * 64 + i * 16 + h2 * 8 + g;
#pragma unroll
                for (int j = 0; j < 4; j++) {
                    const int col = wn * 32 + j * 8 + 2 * tg;
                    float p0 = __expf(sacc[i][j][2 * h2] - nm[i * 2 + h2]);
                    float p1 = __expf(sacc[i][j][2 * h2 + 1] - nm[i * 2 + h2]);
                    ps[i * 2 + h2] += p0 + p1;
                    *(uint2*)&Ps[row * PSP + col] =
                        make_uint2(__float_as_uint(p0), __float_as_uint(p1));
                }
            }
#pragma unroll
        for (int s = 0; s < 8; s++) {
            ps[s] += __shfl_xor_sync(~0u, ps[s], 1);
            ps[s] += __shfl_xor_sync(~0u, ps[s], 2);
            const int row = wm * 64 + (s >> 1) * 16 + (s & 1) * 8 + g;
            if (tg == 0) redS[row * 4 + wn] = ps[s];
        }
        __syncthreads();
#pragma unroll
        for (int s = 0; s < 8; s++) {
            const int row = wm * 64 + (s >> 1) * 16 + (s & 1) * 8 + g;
            const float ts = redS[row * 4] + redS[row * 4 + 1] +
                             redS[row * 4 + 2] + redS[row * 4 + 3];
            l8[s] = alpha[s] * l8[s] + ts;
        }
        // rescale O accumulator
#pragma unroll
        for (int i = 0; i < 4; i++)
#pragma unroll
            for (int j = 0; j < 4; j++) {
                oacc[i][j][0] *= alpha[i * 2];
                oacc[i][j][1] *= alpha[i * 2];
                oacc[i][j][2] *= alpha[i * 2 + 1];
                oacc[i][j][3] *= alpha[i * 2 + 1];
            }

        // ---- O += P @ V tile (4 key-chunks) ----
        for (int c = 0; c < 4; c++, q++) {
            WAITG1();
            __syncthreads();
            if (q + 2 < 128) issue_body(q + 2);
            COMMIT();
            const uint32_t* Bs = BBuf + (q % 3) * BBW;
            const int kb = c * 32;
#pragma unroll
            for (int ks4 = 0; ks4 < 4; ks4++) {
                uint32_t af[4][4], bf[4][2];
                const int kk = kb + ks4 * 8 + tg;
#pragma unroll
                for (int i = 0; i < 4; i++) {
                    const int r0 = wm * 64 + i * 16 + g;
                    af[i][0] = Ps[r0 * PSP + kk];
                    af[i][1] = Ps[(r0 + 8) * PSP + kk];
                    af[i][2] = Ps[r0 * PSP + kk + 4];
                    af[i][3] = Ps[(r0 + 8) * PSP + kk + 4];
                }
                const int kl = ks4 * 8 + tg;
#pragma unroll
                for (int j = 0; j < 4; j++) {
                    const int c0 = wn * 32 + j * 8 + g;
                    bf[j][0] = Bs[kl * BPITCH + c0];
                    bf[j][1] = Bs[(kl + 4) * BPITCH + c0];
                }
#pragma unroll
                for (int i = 0; i < 4; i++)
#pragma unroll
                    for (int j = 0; j < 4; j++) MMA_TF32(oacc[i][j], af[i], bf[j]);
            }
            __syncthreads();
        }
    }

    // ---- epilogue: O / l ----
    float* Oh = O + HB;
#pragma unroll
    for (int i = 0; i < 4; i++) {
        const int row = by * 128 + wm * 64 + i * 16 + g;
        const float inv0 = 1.f / l8[i * 2];
        const float inv1 = 1.f / l8[i * 2 + 1];
#pragma unroll
        for (int j = 0; j < 4; j++) {
            const int col = wn * 32 + j * 8 + 2 * tg;
            *(float2*)(Oh + (size_t)row * DKH + col) =
                make_float2(oacc[i][j][0] * inv0, oacc[i][j][1] * inv0);
            *(float2*)(Oh + (size_t)(row + 8) * DKH + col) =
                make_float2(oacc[i][j][2] * inv1, oacc[i][j][3] * inv1);
        }
    }
}

// ==================== batched tf32 HMMA GEMM (round-5, verified) ============
__global__ __launch_bounds__(256, 2) void tgemm_bat(
    const float* __restrict__ A, const float* __restrict__ B,
    const float* __restrict__ biasvec, float* __restrict__ C,
    int M, int N, int K, size_t sA, size_t sB, size_t sC, size_t sBias,
    int doRelu, int nsplit)
{
    extern __shared__ uint32_t sm[];
    uint32_t* AF = sm;
    uint32_t* BBuf = sm + 2 * AFW1;

    const int tid = threadIdx.x, wid = tid >> 5, lane = tid & 31;
    const int g = lane >> 2, tg = lane & 3, wm = wid >> 2, wn = wid & 3;
    const int batch = blockIdx.z / nsplit, split = blockIdx.z - batch * nsplit;
    const int Keff = K / nsplit, nIter = Keff / BK;

    const float* Ab = A + (size_t)batch * sA + (size_t)split * Keff
                        + (size_t)blockIdx.y * BM * K;
    const float* Bb = B + (size_t)batch * sB + (size_t)split * Keff * N
                        + (size_t)blockIdx.x * BN;
    float* Cb = C + (size_t)blockIdx.z * sC;
    const float* bvv = biasvec ? biasvec + (size_t)batch * sBias : nullptr;

    const int wmS = wid >> 2, iS = wid & 3;
    const float* Ag0 = Ab + (size_t)(wid * 16 + g) * K + tg * 4;
    const float* Ag1 = Ag0 + (size_t)8 * K;
    const int bRow = tid >> 5, bCol = (tid & 31) << 2;
    const float* Bg = Bb + (size_t)bRow * N + bCol;
    const uint32_t bShared = (uint32_t)__cvta_generic_to_shared(BBuf);

    float4 stA[2][2];
    stA[0][0] = *(const float4*)(Ag0);       stA[0][1] = *(const float4*)(Ag0 + 16);
    stA[1][0] = *(const float4*)(Ag1);       stA[1][1] = *(const float4*)(Ag1 + 16);
    storeA_frag(AF, stA, wmS, iS, g, tg);
#pragma unroll
    for (int rh = 0; rh < 32; rh += 8)
        cpasync16(bShared + (((bRow + rh) * BPITCH + bCol) << 2), Bg + (size_t)rh * N);
    COMMIT();
    stA[0][0] = *(const float4*)(Ag0 + BK);  stA[0][1] = *(const float4*)(Ag0 + BK + 16);
    stA[1][0] = *(const float4*)(Ag1 + BK);  stA[1][1] = *(const float4*)(Ag1 + BK + 16);
    {
        const float* Bn = Bg + (size_t)BK * N;
        const uint32_t db = bShared + (BBW << 2);
#pragma unroll
        for (int rh = 0; rh < 32; rh += 8)
            cpasync16(db + (((bRow + rh) * BPITCH + bCol) << 2), Bn + (size_t)rh * N);
    }
    COMMIT();

    float acc[4][4][4];
#pragma unroll
    for (int i = 0; i < 4; i++)
#pragma unroll
        for (int j = 0; j < 4; j++)
#pragma unroll
            for (int r = 0; r < 4; r++) acc[i][j][r] = 0.f;

    for (int it = 0; it < nIter; it++) {
        WAITG1();
        __syncthreads();
        if (it + 2 < nIter) {
            const float* Bn = Bg + (size_t)(it + 2) * BK * N;
            const uint32_t db = bShared + (((it + 2) % 3) * BBW << 2);
#pragma unroll
            for (int rh = 0; rh < 32; rh += 8)
                cpasync16(db + (((bRow + rh) * BPITCH + bCol) << 2), Bn + (size_t)rh * N);
        }
        COMMIT();
        if (it + 1 < nIter)
            storeA_frag(AF + ((it + 1) & 1) * AFW1, stA, wmS, iS, g, tg);
        if (it + 2 < nIter) {
            const float* An0 = Ag0 + (size_t)(it + 2) * BK;
            const float* An1 = Ag1 + (size_t)(it + 2) * BK;
            stA[0][0] = *(const float4*)(An0);  stA[0][1] = *(const float4*)(An0 + 16);
            stA[1][0] = *(const float4*)(An1);  stA[1][1] = *(const float4*)(An1 + 16);
        }
        const uint32_t* AFr = AF + (it & 1) * AFW1;
        const uint32_t* Bs = BBuf + (it % 3) * BBW;
#pragma unroll
        for (int ks4 = 0; ks4 < 4; ks4++) {
            uint32_t af[4][4], bf[4][2];
#pragma unroll
            for (int i = 0; i < 4; i++) {
                const uint4 qd = *(const uint4*)
                    &AFr[(((wm * 4 + ks4) * 4 + i) * 32 + (lane ^ (g & 3))) * 4];
                af[i][0] = qd.x; af[i][1] = qd.y; af[i][2] = qd.z; af[i][3] = qd.w;
            }
            const int kl = ks4 * 8 + tg;
#pragma unroll
            for (int j = 0; j < 4; j++) {
                const int c0 = wn * 32 + j * 8 + g;
                bf[j][0] = Bs[kl * BPITCH + c0];
                bf[j][1] = Bs[(kl + 4) * BPITCH + c0];
            }
#pragma unroll
            for (int i = 0; i < 4; i++)
#pragma unroll
                for (int j = 0; j < 4; j++) MMA_TF32(acc[i][j], af[i], bf[j]);
        }
        __syncthreads();
    }

#pragma unroll
    for (int i = 0; i < 4; i++) {
        const int row = blockIdx.y * BM + wm * 64 + i * 16 + g;
#pragma unroll
        for (int j = 0; j < 4; j++) {
            const int col = blockIdx.x * BN + wn * 32 + j * 8 + 2 * tg;
            float v0 = acc[i][j][0], v1 = acc[i][j][1];
            float v2 = acc[i][j][2], v3 = acc[i][j][3];
            if (bvv) {
                v0 += bvv[col]; v1 += bvv[col + 1];
                v2 += bvv[col]; v3 += bvv[col + 1];
            }
            if (doRelu) {
                v0 = fmaxf(v0, 0.f); v1 = fmaxf(v1, 0.f);
                v2 = fmaxf(v2, 0.f); v3 = fmaxf(v3, 0.f);
            }
            *(float2*)(Cb + (size_t)row * N + col) = make_float2(v0, v1);
            *(float2*)(Cb + (size_t)(row + 8) * N + col) = make_float2(v2, v3);
        }
    }
}

// ---- split-K reduce ----
__global__ void reduceK_k(const float4* __restrict__ part, float4* __restrict__ outp,
                          const float* __restrict__ bias, int nsplit, size_t MN4, int N4)
{
    const size_t i = (size_t)blockIdx.x * blockDim.x + threadIdx.x;
    const size_t b = i / MN4, e = i - b * MN4;
    const float4* p = part + b * (size_t)nsplit * MN4 + e;
    float4 a = p[0];
    for (int s = 1; s < nsplit; s++) {
        const float4 v = p[(size_t)s * MN4];
        a.x += v.x; a.y += v.y; a.z += v.z; a.w += v.w;
    }
    if (bias) {
        const float4 bb = ((const float4*)bias)[e % N4];
        a.x += bb.x; a.y += bb.y; a.z += bb.z; a.w += bb.w;
    }
    outp[i] = a;
}

// ---- x2 = x + deg embeddings ----
__global__ void addemb_k(const float* __restrict__ x, const int* __restrict__ ind,
                         const int* __restrict__ outd, const float* __restrict__ ie,
                         const float* __restrict__ oe, float* __restrict__ x2)
{
    const int n = blockIdx.x;
    const float4* xr = (const float4*)(x + (size_t)n * DMOD);
    const float4* ir = (const float4*)(ie + (size_t)ind[n] * DMOD);
    const float4* orr = (const float4*)(oe + (size_t)outd[n] * DMOD);
    const int i = threadIdx.x;
    float4 a = xr[i], b = ir[i], c = orr[i];
    a.x += b.x + c.x; a.y += b.y + c.y; a.z += b.z + c.z; a.w += b.w + c.w;
    ((float4*)(x2 + (size_t)n * DMOD))[i] = a;
}

__global__ void etw_k(const float* __restrict__ re, const float* __restrict__ rw,
                      float* __restrict__ etw)
{
    const int t = threadIdx.x;
    float s = 0.f;
    for (int j = 0; j < DKH; j++) s += re[t * DKH + j] * rw[t * DKH + j];
    etw[t] = s * SCALE;
}

__global__ void bias2d_k(const int* __restrict__ dist, const int4* __restrict__ pet,
                         const float4* __restrict__ paw, const float* __restrict__ plen,
                         const float* __restrict__ etw, float* __restrict__ out)
{
    const size_t i = (size_t)blockIdx.x * blockDim.x + threadIdx.x;
    const int4 e = pet[i];
    const float4 w = paw[i];
    float b = plen[dist[i]];
    b += etw[e.x] * w.x + etw[e.y] * w.y + etw[e.z] * w.z + etw[e.w] * w.w;
    out[i] = b;
}

__global__ void add_ln_k(const float* __restrict__ a, const float* __restrict__ c,
                         const float* __restrict__ g, const float* __restrict__ b,
                         float* __restrict__ y)
{
    const int n = blockIdx.x;
    const float* ar = a + (size_t)n * DMOD;
    const float* cr = c + (size_t)n * DMOD;
    float* yr = y + (size_t)n * DMOD;
    __shared__ float r1[256], r2[256];
    float s = 0.f, s2 = 0.f;
    for (int i = threadIdx.x; i < DMOD; i += 256) {
        float v = ar[i] + cr[i];
        s += v; s2 += v * v;
    }
    r1[threadIdx.x] = s; r2[threadIdx.x] = s2;
    __syncthreads();
    for (int st = 128; st > 0; st >>= 1) {
        if (threadIdx.x < st) {
            r1[threadIdx.x] += r1[threadIdx.x + st];
            r2[threadIdx.x] += r2[threadIdx.x + st];
        }
        __syncthreads();
    }
    const float mean = r1[0] * (1.f / DMOD);
    const float var = r2[0] * (1.f / DMOD) - mean * mean;
    const float rstd = rsqrtf(var + 1e-5f);
    for (int i = threadIdx.x; i < DMOD; i += 256) {
        float v = ar[i] + cr[i];
        yr[i] = (v - mean) * rstd * g[i] + b[i];
    }
}

// ---------------------------------------------------------------------------
extern "C" void kernel_launch(void* const* d_in, const int* in_sizes, int n_in,
                              void* d_out, int out_size)
{
    const float* x      = (const float*)d_in[0];
    const float* lgx    = (const float*)d_in[1];
    const int* in_deg   = (const int*)d_in[2];
    const int* out_deg  = (const int*)d_in[3];
    const int* dist     = (const int*)d_in[4];
    const int* pet      = (const int*)d_in[5];
    const float* paw    = (const float*)d_in[6];
    const float* rel_e  = (const float*)d_in[7];
    const float* rel_w  = (const float*)d_in[8];
    const float* ide    = (const float*)d_in[9];
    const float* ode    = (const float*)d_in[10];
    const float* plen   = (const float*)d_in[11];
    const float* Wq = (const float*)d_in[12];  const float* bq = (const float*)d_in[13];
    const float* Wk = (const float*)d_in[14];  const float* bk = (const float*)d_in[15];
    const float* Wv = (const float*)d_in[16];  const float* bv = (const float*)d_in[17];
    const float* Wo = (const float*)d_in[18];  const float* bo = (const float*)d_in[19];
    const float* ln1g = (const float*)d_in[20]; const float* ln1b = (const float*)d_in[21];
    const float* W1 = (const float*)d_in[22];  const float* b1 = (const float*)d_in[23];
    const float* W2 = (const float*)d_in[24];  const float* b2 = (const float*)d_in[25];
    const float* ln2g = (const float*)d_in[26]; const float* ln2b = (const float*)d_in[27];
    float* out = (float*)d_out;

    float *x2, *bias2d, *Wqkv, *bqkv, *qkv, *ao, *t, *h1, *ff, *part, *etw;
    cudaGetSymbolAddress((void**)&x2, g_x2);
    cudaGetSymbolAddress((void**)&bias2d, g_bias2d);
    cudaGetSymbolAddress((void**)&Wqkv, g_Wqkv);
    cudaGetSymbolAddress((void**)&bqkv, g_bqkv);
    cudaGetSymbolAddress((void**)&qkv, g_qkv);
    cudaGetSymbolAddress((void**)&ao, g_ao);
    cudaGetSymbolAddress((void**)&t, g_t);
    cudaGetSymbolAddress((void**)&h1, g_h1);
    cudaGetSymbolAddress((void**)&ff, g_ff);
    cudaGetSymbolAddress((void**)&part, g_part);
    cudaGetSymbolAddress((void**)&etw, g_etw);

    cudaFuncSetAttribute(tgemm_bat, cudaFuncAttributeMaxDynamicSharedMemorySize,
                         GSMEM_BYTES);
    cudaFuncSetAttribute(flash_k, cudaFuncAttributeMaxDynamicSharedMemorySize,
                         FLASH_SMEM);

    const size_t WB = (size_t)DMOD * DMOD * sizeof(float);

    cudaMemcpyAsync(out + (size_t)NTOK * DMOD, lgx,
                    (size_t)NTOK * 8 * DMOD * sizeof(float), cudaMemcpyDeviceToDevice);
    cudaMemcpyAsync(Wqkv,            Wq, WB, cudaMemcpyDeviceToDevice);
    cudaMemcpyAsync(Wqkv + WB / 4,   Wk, WB, cudaMemcpyDeviceToDevice);
    cudaMemcpyAsync(Wqkv + WB / 2,   Wv, WB, cudaMemcpyDeviceToDevice);
    cudaMemcpyAsync(bqkv,            bq, DMOD * 4, cudaMemcpyDeviceToDevice);
    cudaMemcpyAsync(bqkv + DMOD,     bk, DMOD * 4, cudaMemcpyDeviceToDevice);
    cudaMemcpyAsync(bqkv + 2 * DMOD, bv, DMOD * 4, cudaMemcpyDeviceToDevice);

    addemb_k<<<NTOK, 256>>>(x, in_deg, out_deg, ide, ode, x2);
    etw_k<<<1, 64>>>(rel_e, rel_w, etw);
    bias2d_k<<<(NTOK * NTOK) / 256, 256>>>(dist, (const int4*)pet, (const float4*)paw,
                                           plen, etw, bias2d);

    const size_t ND = (size_t)NTOK * DMOD;
    float* q = qkv;
    float* k = qkv + ND;
    float* v = qkv + 2 * ND;

    // Q/K/V projections batched
    tgemm_bat<<<dim3(8, 16, 3), 256, GSMEM_BYTES>>>(
        x2, Wqkv, bqkv, qkv, NTOK, DMOD, DMOD,
        0, (size_t)DMOD * DMOD, ND, DMOD, 0, 1);

    // fused attention: QK + bias + softmax + PV -> ao
    flash_k<<<dim3(1, 16, HEADS), 256, FLASH_SMEM>>>(q, k, v, bias2d, ao);

    // output projection split-K=2 + reduce(+bo) + LN1
    tgemm_bat<<<dim3(8, 16, 2), 256, GSMEM_BYTES>>>(
        ao, Wo, nullptr, part, NTOK, DMOD, DMOD, 0, 0, ND, 0, 0, 2);
    reduceK_k<<<(NTOK * DMOD / 4) / 256, 256>>>(
        (const float4*)part, (float4*)t, bo, 2, ND / 4, DMOD / 4);
    add_ln_k<<<NTOK, 256>>>(x2, t, ln1g, ln1b, h1);

    // FFN1 (+b1, relu)
    tgemm_bat<<<dim3(32, 16, 1), 256, GSMEM_BYTES>>>(
        h1, W1, b1, ff, NTOK, FFD, DMOD, 0, 0, 0, FFD, 1, 1);
    // FFN2 split-K=2 + reduce(+b2) + LN2
    tgemm_bat<<<dim3(8, 16, 2), 256, GSMEM_BYTES>>>(
        ff, W2, nullptr, part, NTOK, DMOD, FFD, 0, 0, ND, 0, 0, 2);
    reduceK_k<<<(NTOK * DMOD / 4) / 256, 256>>>(
        (const float4*)part, (float4*)t, b2, 2, ND / 4, DMOD / 4);
    add_ln_k<<<NTOK, 256>>>(h1, t, ln2g, ln2b, out);
}

// round 9
// speedup vs baseline: 1.0843x; 1.0026x over previous
#include <cuda_runtime.h>
#include <cstdint>
#include <cstddef>

// ---------------------------------------------------------------------------
// Rel_Transformer_Layer: N=2048, D=1024, H=8, DK=128, L=4, FF=4096
// Round 9: round-8 flash pipeline + QKV split-K=2 (wave quantization) +
// side-stream overlap of bias2d/lgx under QKV (graph fork-join).
// ---------------------------------------------------------------------------

#define NTOK 2048
#define DMOD 1024
#define HEADS 8
#define DKH 128
#define FFD 4096
#define SCALE 0.08838834764831845f  // 1/sqrt(128)

// -------------------- scratch (static device allocations) ------------------
__device__ float g_x2[NTOK * DMOD];
__device__ float g_bias2d[(size_t)NTOK * NTOK];
__device__ float g_Wqkv[3 * DMOD * DMOD];
__device__ float g_bqkv[3 * DMOD];
__device__ float g_qkv[3 * NTOK * DMOD];
__device__ float g_ao[NTOK * DMOD];
__device__ float g_t[NTOK * DMOD];
__device__ float g_h1[NTOK * DMOD];
__device__ float g_ff[(size_t)NTOK * FFD];
__device__ float g_part[(size_t)6 * NTOK * DMOD];   // 48 MB split-K partials
__device__ float g_etw[64];

// -------------------- helpers ----------------------------------------------
__device__ __forceinline__ uint32_t f2tf(float f) {
    uint32_t u; asm("cvt.rna.tf32.f32 %0, %1;" : "=r"(u) : "f"(f)); return u;
}
__device__ __forceinline__ void cpasync16(uint32_t s, const void* g) {
    asm volatile("cp.async.cg.shared.global [%0], [%1], 16;" :: "r"(s), "l"(g));
}
#define COMMIT() asm volatile("cp.async.commit_group;" ::: "memory")
#define WAITG1() asm volatile("cp.async.wait_group 1;" ::: "memory")

#define BM 128
#define BN 128
#define BK 32
#define BPITCH 136
#define AFW1 4096
#define BBW (32 * BPITCH)
#define GSMEM_BYTES ((2 * AFW1 + 3 * BBW) * 4)

__device__ __forceinline__ void storeA_frag(
    uint32_t* AFb, const float4 stA[2][2], int wmS, int iS, int g, int tg)
{
#pragma unroll
    for (int h = 0; h < 2; h++) {
        const int ks4h = (tg >> 1) + 2 * h;
        const int hk = tg & 1;
#pragma unroll
        for (int cc = 0; cc < 4; cc++) {
            const int lane_sw = (g * 4 + cc) ^ (g & 3);
            const int word = (((wmS * 4 + ks4h) * 4 + iS) * 32 + lane_sw) * 4 + 2 * hk;
            uint32_t v0 = f2tf(((const float*)&stA[0][h])[cc]);
            uint32_t v1 = f2tf(((const float*)&stA[1][h])[cc]);
            *(uint2*)&AFb[word] = make_uint2(v0, v1);
        }
    }
}

#define MMA_TF32(acc, af, bf)                                              \
    asm volatile(                                                          \
        "mma.sync.aligned.m16n8k8.row.col.f32.tf32.tf32.f32 "              \
        "{%0,%1,%2,%3}, {%4,%5,%6,%7}, {%8,%9}, {%0,%1,%2,%3};"            \
        : "+f"(acc[0]), "+f"(acc[1]), "+f"(acc[2]), "+f"(acc[3])           \
        : "r"(af[0]), "r"(af[1]), "r"(af[2]), "r"(af[3]),                  \
          "r"(bf[0]), "r"(bf[1]))

// ==================== flash attention (round-8, verified) ====================
#define PSP 132
#define FL_BBUF 16384
#define FL_PS   29440
#define FL_REDM 46336
#define FLASH_SMEM (47360 * 4)

__global__ __launch_bounds__(256, 1) void flash_k(
    const float* __restrict__ Q, const float* __restrict__ Km,
    const float* __restrict__ V, const float* __restrict__ bias2d,
    float* __restrict__ O)
{
    extern __shared__ uint32_t sm[];
    uint32_t* AFQ = sm;
    uint32_t* BBuf = sm + FL_BBUF;
    uint32_t* Ps = sm + FL_PS;
    float* redM = (float*)(sm + FL_REDM);
    float* redS = redM + 512;

    const int tid = threadIdx.x, wid = tid >> 5, lane = tid & 31;
    const int g = lane >> 2, tg = lane & 3, wm = wid >> 2, wn = wid & 3;
    const int h = blockIdx.z, by = blockIdx.y;
    const size_t HB = (size_t)h * 256 * DMOD;

    const float* Qh = Q + HB;
    const float* Kh = Km + HB;
    const float* Vh = V + HB;

    const int bRow = tid >> 5, bCol = (tid & 31) << 2;
    const uint32_t bSh = (uint32_t)__cvta_generic_to_shared(BBuf);
    auto issue_body = [&](int qq) {
        const int t = qq >> 3, ph = qq & 7;
        const float* src;
        int stride;
        if (ph < 4) { src = Kh + (size_t)(ph * 32 + bRow) * NTOK + t * 128 + bCol; stride = NTOK; }
        else        { src = Vh + (size_t)(t * 128 + (ph - 4) * 32 + bRow) * DKH + bCol; stride = DKH; }
        const uint32_t db = bSh + ((qq % 3) * BBW << 2);
#pragma unroll
        for (int rh = 0; rh < 32; rh += 8)
            cpasync16(db + (((bRow + rh) * BPITCH + bCol) << 2), src + (size_t)rh * stride);
    };
    issue_body(0); COMMIT();
    issue_body(1); COMMIT();

    {
        const int wmS = wid >> 2, iS = wid & 3;
        const float* Qg0 = Qh + (size_t)(by * 128 + wid * 16 + g) * DKH + tg * 4;
        const float* Qg1 = Qg0 + 8 * DKH;
#pragma unroll
        for (int c = 0; c < 4; c++) {
            float4 stA[2][2];
            stA[0][0] = *(const float4*)(Qg0 + c * 32);
            stA[0][1] = *(const float4*)(Qg0 + c * 32 + 16);
            stA[1][0] = *(const float4*)(Qg1 + c * 32);
            stA[1][1] = *(const float4*)(Qg1 + c * 32 + 16);
            storeA_frag(AFQ + c * 4096, stA, wmS, iS, g, tg);
        }
    }

    float m8[8], l8[8], oacc[4][4][4];
#pragma unroll
    for (int s = 0; s < 8; s++) { m8[s] = -1e30f; l8[s] = 0.f; }
#pragma unroll
    for (int i = 0; i < 4; i++)
#pragma unroll
        for (int j = 0; j < 4; j++)
#pragma unroll
            for (int r = 0; r < 4; r++) oacc[i][j][r] = 0.f;

    int q = 0;
    for (int t = 0; t < 16; t++) {
        float sacc[4][4][4];
#pragma unroll
        for (int i = 0; i < 4; i++)
#pragma unroll
            for (int j = 0; j < 4; j++)
#pragma unroll
                for (int r = 0; r < 4; r++) sacc[i][j][r] = 0.f;

        for (int c = 0; c < 4; c++, q++) {
            WAITG1();
            __syncthreads();
            if (q + 2 < 128) issue_body(q + 2);
            COMMIT();
            const uint32_t* AFr = AFQ + c * 4096;
            const uint32_t* Bs = BBuf + (q % 3) * BBW;
#pragma unroll
            for (int ks4 = 0; ks4 < 4; ks4++) {
                uint32_t af[4][4], bf[4][2];
#pragma unroll
                for (int i = 0; i < 4; i++) {
                    const uint4 qd = *(const uint4*)
                        &AFr[(((wm * 4 + ks4) * 4 + i) * 32 + (lane ^ (g & 3))) * 4];
                    af[i][0] = qd.x; af[i][1] = qd.y; af[i][2] = qd.z; af[i][3] = qd.w;
                }
                const int kl = ks4 * 8 + tg;
#pragma unroll
                for (int j = 0; j < 4; j++) {
                    const int c0 = wn * 32 + j * 8 + g;
                    bf[j][0] = Bs[kl * BPITCH + c0];
                    bf[j][1] = Bs[(kl + 4) * BPITCH + c0];
                }
#pragma unroll
                for (int i = 0; i < 4; i++)
#pragma unroll
                    for (int j = 0; j < 4; j++) MMA_TF32(sacc[i][j], af[i], bf[j]);
            }
            __syncthreads();
        }

#pragma unroll
        for (int i = 0; i < 4; i++) {
            const int rg = by * 128 + wm * 64 + i * 16 + g;
#pragma unroll
            for (int j = 0; j < 4; j++) {
                const int cg = t * 128 + wn * 32 + j * 8 + 2 * tg;
                const float2 b0 = *(const float2*)(bias2d + (size_t)rg * NTOK + cg);
                const float2 b1 = *(const float2*)(bias2d + (size_t)(rg + 8) * NTOK + cg);
                sacc[i][j][0] = sacc[i][j][0] * SCALE + b0.x;
                sacc[i][j][1] = sacc[i][j][1] * SCALE + b0.y;
                sacc[i][j][2] = sacc[i][j][2] * SCALE + b1.x;
                sacc[i][j][3] = sacc[i][j][3] * SCALE + b1.y;
            }
        }

        float pm[8];
#pragma unroll
        for (int i = 0; i < 4; i++)
#pragma unroll
            for (int h2 = 0; h2 < 2; h2++) {
                float v = -1e30f;
#pragma unroll
                for (int j = 0; j < 4; j++)
                    v = fmaxf(v, fmaxf(sacc[i][j][2 * h2], sacc[i][j][2 * h2 + 1]));
                pm[i * 2 + h2] = v;
            }
#pragma unroll
        for (int s = 0; s < 8; s++) {
            pm[s] = fmaxf(pm[s], __shfl_xor_sync(~0u, pm[s], 1));
            pm[s] = fmaxf(pm[s], __shfl_xor_sync(~0u, pm[s], 2));
        }
#pragma unroll
        for (int s = 0; s < 8; s++) {
            const int row = wm * 64 + (s >> 1) * 16 + (s & 1) * 8 + g;
            if (tg == 0) redM[row * 4 + wn] = pm[s];
        }
        __syncthreads();

        float alpha[8], nm[8];
#pragma unroll
        for (int s = 0; s < 8; s++) {
            const int row = wm * 64 + (s >> 1) * 16 + (s & 1) * 8 + g;
            float tm = fmaxf(fmaxf(redM[row * 4], redM[row * 4 + 1]),
                             fmaxf(redM[row * 4 + 2], redM[row * 4 + 3]));
            nm[s] = fmaxf(m8[s], tm);
            alpha[s] = __expf(m8[s] - nm[s]);
            m8[s] = nm[s];
        }

        float ps[8];
#pragma unroll
        for (int s = 0; s < 8; s++) ps[s] = 0.f;
#pragma unroll
        for (int i = 0; i < 4; i++)
#pragma unroll
            for (int h2 = 0; h2 < 2; h2++) {
                const int row = wm * 64 + i * 16 + h2 * 8 + g;
#pragma unroll
                for (int j = 0; j < 4; j++) {
                    const int col = wn * 32 + j * 8 + 2 * tg;
                    float p0 = __expf(sacc[i][j][2 * h2] - nm[i * 2 + h2]);
                    float p1 = __expf(sacc[i][j][2 * h2 + 1] - nm[i * 2 + h2]);
                    ps[i * 2 + h2] += p0 + p1;
                    *(uint2*)&Ps[row * PSP + col] =
                        make_uint2(__float_as_uint(p0), __float_as_uint(p1));
                }
            }
#pragma unroll
        for (int s = 0; s < 8; s++) {
            ps[s] += __shfl_xor_sync(~0u, ps[s], 1);
            ps[s] += __shfl_xor_sync(~0u, ps[s], 2);
            const int row = wm * 64 + (s >> 1) * 16 + (s & 1) * 8 + g;
            if (tg == 0) redS[row * 4 + wn] = ps[s];
        }
        __syncthreads();
#pragma unroll
        for (int s = 0; s < 8; s++) {
            const int row = wm * 64 + (s >> 1) * 16 + (s & 1) * 8 + g;
            const float ts = redS[row * 4] + redS[row * 4 + 1] +
                             redS[row * 4 + 2] + redS[row * 4 + 3];
            l8[s] = alpha[s] * l8[s] + ts;
        }
#pragma unroll
        for (int i = 0; i < 4; i++)
#pragma unroll
            for (int j = 0; j < 4; j++) {
                oacc[i][j][0] *= alpha[i * 2];
                oacc[i][j][1] *= alpha[i * 2];
                oacc[i][j][2] *= alpha[i * 2 + 1];
                oacc[i][j][3] *= alpha[i * 2 + 1];
            }

        for (int c = 0; c < 4; c++, q++) {
            WAITG1();
            __syncthreads();
            if (q + 2 < 128) issue_body(q + 2);
            COMMIT();
            const uint32_t* Bs = BBuf + (q % 3) * BBW;
            const int kb = c * 32;
#pragma unroll
            for (int ks4 = 0; ks4 < 4; ks4++) {
                uint32_t af[4][4], bf[4][2];
                const int kk = kb + ks4 * 8 + tg;
#pragma unroll
                for (int i = 0; i < 4; i++) {
                    const int r0 = wm * 64 + i * 16 + g;
                    af[i][0] = Ps[r0 * PSP + kk];
                    af[i][1] = Ps[(r0 + 8) * PSP + kk];
                    af[i][2] = Ps[r0 * PSP + kk + 4];
                    af[i][3] = Ps[(r0 + 8) * PSP + kk + 4];
                }
                const int kl = ks4 * 8 + tg;
#pragma unroll
                for (int j = 0; j < 4; j++) {
                    const int c0 = wn * 32 + j * 8 + g;
                    bf[j][0] = Bs[kl * BPITCH + c0];
                    bf[j][1] = Bs[(kl + 4) * BPITCH + c0];
                }
#pragma unroll
                for (int i = 0; i < 4; i++)
#pragma unroll
                    for (int j = 0; j < 4; j++) MMA_TF32(oacc[i][j], af[i], bf[j]);
            }
            __syncthreads();
        }
    }

    float* Oh = O + HB;
#pragma unroll
    for (int i = 0; i < 4; i++) {
        const int row = by * 128 + wm * 64 + i * 16 + g;
        const float inv0 = 1.f / l8[i * 2];
        const float inv1 = 1.f / l8[i * 2 + 1];
#pragma unroll
        for (int j = 0; j < 4; j++) {
            const int col = wn * 32 + j * 8 + 2 * tg;
            *(float2*)(Oh + (size_t)row * DKH + col) =
                make_float2(oacc[i][j][0] * inv0, oacc[i][j][1] * inv0);
            *(float2*)(Oh + (size_t)(row + 8) * DKH + col) =
                make_float2(oacc[i][j][2] * inv1, oacc[i][j][3] * inv1);
        }
    }
}

// ==================== batched tf32 HMMA GEMM (verified) ====================
__global__ __launch_bounds__(256, 2) void tgemm_bat(
    const float* __restrict__ A, const float* __restrict__ B,
    const float* __restrict__ biasvec, float* __restrict__ C,
    int M, int N, int K, size_t sA, size_t sB, size_t sC, size_t sBias,
    int doRelu, int nsplit)
{
    extern __shared__ uint32_t sm[];
    uint32_t* AF = sm;
    uint32_t* BBuf = sm + 2 * AFW1;

    const int tid = threadIdx.x, wid = tid >> 5, lane = tid & 31;
    const int g = lane >> 2, tg = lane & 3, wm = wid >> 2, wn = wid & 3;
    const int batch = blockIdx.z / nsplit, split = blockIdx.z - batch * nsplit;
    const int Keff = K / nsplit, nIter = Keff / BK;

    const float* Ab = A + (size_t)batch * sA + (size_t)split * Keff
                        + (size_t)blockIdx.y * BM * K;
    const float* Bb = B + (size_t)batch * sB + (size_t)split * Keff * N
                        + (size_t)blockIdx.x * BN;
    float* Cb = C + (size_t)blockIdx.z * sC;
    const float* bvv = biasvec ? biasvec + (size_t)batch * sBias : nullptr;

    const int wmS = wid >> 2, iS = wid & 3;
    const float* Ag0 = Ab + (size_t)(wid * 16 + g) * K + tg * 4;
    const float* Ag1 = Ag0 + (size_t)8 * K;
    const int bRow = tid >> 5, bCol = (tid & 31) << 2;
    const float* Bg = Bb + (size_t)bRow * N + bCol;
    const uint32_t bShared = (uint32_t)__cvta_generic_to_shared(BBuf);

    float4 stA[2][2];
    stA[0][0] = *(const float4*)(Ag0);       stA[0][1] = *(const float4*)(Ag0 + 16);
    stA[1][0] = *(const float4*)(Ag1);       stA[1][1] = *(const float4*)(Ag1 + 16);
    storeA_frag(AF, stA, wmS, iS, g, tg);
#pragma unroll
    for (int rh = 0; rh < 32; rh += 8)
        cpasync16(bShared + (((bRow + rh) * BPITCH + bCol) << 2), Bg + (size_t)rh * N);
    COMMIT();
    stA[0][0] = *(const float4*)(Ag0 + BK);  stA[0][1] = *(const float4*)(Ag0 + BK + 16);
    stA[1][0] = *(const float4*)(Ag1 + BK);  stA[1][1] = *(const float4*)(Ag1 + BK + 16);
    {
        const float* Bn = Bg + (size_t)BK * N;
        const uint32_t db = bShared + (BBW << 2);
#pragma unroll
        for (int rh = 0; rh < 32; rh += 8)
            cpasync16(db + (((bRow + rh) * BPITCH + bCol) << 2), Bn + (size_t)rh * N);
    }
    COMMIT();

    float acc[4][4][4];
#pragma unroll
    for (int i = 0; i < 4; i++)
#pragma unroll
        for (int j = 0; j < 4; j++)
#pragma unroll
            for (int r = 0; r < 4; r++) acc[i][j][r] = 0.f;

    for (int it = 0; it < nIter; it++) {
        WAITG1();
        __syncthreads();
        if (it + 2 < nIter) {
            const float* Bn = Bg + (size_t)(it + 2) * BK * N;
            const uint32_t db = bShared + (((it + 2) % 3) * BBW << 2);
#pragma unroll
            for (int rh = 0; rh < 32; rh += 8)
                cpasync16(db + (((bRow + rh) * BPITCH + bCol) << 2), Bn + (size_t)rh * N);
        }
        COMMIT();
        if (it + 1 < nIter)
            storeA_frag(AF + ((it + 1) & 1) * AFW1, stA, wmS, iS, g, tg);
        if (it + 2 < nIter) {
            const float* An0 = Ag0 + (size_t)(it + 2) * BK;
            const float* An1 = Ag1 + (size_t)(it + 2) * BK;
            stA[0][0] = *(const float4*)(An0);  stA[0][1] = *(const float4*)(An0 + 16);
            stA[1][0] = *(const float4*)(An1);  stA[1][1] = *(const float4*)(An1 + 16);
        }
        const uint32_t* AFr = AF + (it & 1) * AFW1;
        const uint32_t* Bs = BBuf + (it % 3) * BBW;
#pragma unroll
        for (int ks4 = 0; ks4 < 4; ks4++) {
            uint32_t af[4][4], bf[4][2];
#pragma unroll
            for (int i = 0; i < 4; i++) {
                const uint4 qd = *(const uint4*)
                    &AFr[(((wm * 4 + ks4) * 4 + i) * 32 + (lane ^ (g & 3))) * 4];
                af[i][0] = qd.x; af[i][1] = qd.y; af[i][2] = qd.z; af[i][3] = qd.w;
            }
            const int kl = ks4 * 8 + tg;
#pragma unroll
            for (int j = 0; j < 4; j++) {
                const int c0 = wn * 32 + j * 8 + g;
                bf[j][0] = Bs[kl * BPITCH + c0];
                bf[j][1] = Bs[(kl + 4) * BPITCH + c0];
            }
#pragma unroll
            for (int i = 0; i < 4; i++)
#pragma unroll
                for (int j = 0; j < 4; j++) MMA_TF32(acc[i][j], af[i], bf[j]);
        }
        __syncthreads();
    }

#pragma unroll
    for (int i = 0; i < 4; i++) {
        const int row = blockIdx.y * BM + wm * 64 + i * 16 + g;
#pragma unroll
        for (int j = 0; j < 4; j++) {
            const int col = blockIdx.x * BN + wn * 32 + j * 8 + 2 * tg;
            float v0 = acc[i][j][0], v1 = acc[i][j][1];
            float v2 = acc[i][j][2], v3 = acc[i][j][3];
            if (bvv) {
                v0 += bvv[col]; v1 += bvv[col + 1];
                v2 += bvv[col]; v3 += bvv[col + 1];
            }
            if (doRelu) {
                v0 = fmaxf(v0, 0.f); v1 = fmaxf(v1, 0.f);
                v2 = fmaxf(v2, 0.f); v3 = fmaxf(v3, 0.f);
            }
            *(float2*)(Cb + (size_t)row * N + col) = make_float2(v0, v1);
            *(float2*)(Cb + (size_t)(row + 8) * N + col) = make_float2(v2, v3);
        }
    }
}

// ---- split-K reduce: out[b][e] = sum_s part[b][s][e] (+bias[b]) ----
__global__ void reduceK_k(const float4* __restrict__ part, float4* __restrict__ outp,
                          const float* __restrict__ bias, int nsplit, size_t MN4,
                          int N4, int sB4)
{
    const size_t i = (size_t)blockIdx.x * blockDim.x + threadIdx.x;
    const size_t b = i / MN4, e = i - b * MN4;
    const float4* p = part + b * (size_t)nsplit * MN4 + e;
    float4 a = p[0];
    for (int s = 1; s < nsplit; s++) {
        const float4 v = p[(size_t)s * MN4];
        a.x += v.x; a.y += v.y; a.z += v.z; a.w += v.w;
    }
    if (bias) {
        const float4 bb = ((const float4*)bias)[b * sB4 + (e % N4)];
        a.x += bb.x; a.y += bb.y; a.z += bb.z; a.w += bb.w;
    }
    outp[i] = a;
}

// ---- x2 = x + deg embeddings ----
__global__ void addemb_k(const float* __restrict__ x, const int* __restrict__ ind,
                         const int* __restrict__ outd, const float* __restrict__ ie,
                         const float* __restrict__ oe, float* __restrict__ x2)
{
    const int n = blockIdx.x;
    const float4* xr = (const float4*)(x + (size_t)n * DMOD);
    const float4* ir = (const float4*)(ie + (size_t)ind[n] * DMOD);
    const float4* orr = (const float4*)(oe + (size_t)outd[n] * DMOD);
    const int i = threadIdx.x;
    float4 a = xr[i], b = ir[i], c = orr[i];
    a.x += b.x + c.x; a.y += b.y + c.y; a.z += b.z + c.z; a.w += b.w + c.w;
    ((float4*)(x2 + (size_t)n * DMOD))[i] = a;
}

__global__ void etw_k(const float* __restrict__ re, const float* __restrict__ rw,
                      float* __restrict__ etw)
{
    const int t = threadIdx.x;
    float s = 0.f;
    for (int j = 0; j < DKH; j++) s += re[t * DKH + j] * rw[t * DKH + j];
    etw[t] = s * SCALE;
}

__global__ void bias2d_k(const int* __restrict__ dist, const int4* __restrict__ pet,
                         const float4* __restrict__ paw, const float* __restrict__ plen,
                         const float* __restrict__ etw, float* __restrict__ out)
{
    const size_t i = (size_t)blockIdx.x * blockDim.x + threadIdx.x;
    const int4 e = pet[i];
    const float4 w = paw[i];
    float b = plen[dist[i]];
    b += etw[e.x] * w.x + etw[e.y] * w.y + etw[e.z] * w.z + etw[e.w] * w.w;
    out[i] = b;
}

__global__ void add_ln_k(const float* __restrict__ a, const float* __restrict__ c,
                         const float* __restrict__ g, const float* __restrict__ b,
                         float* __restrict__ y)
{
    const int n = blockIdx.x;
    const float* ar = a + (size_t)n * DMOD;
    const float* cr = c + (size_t)n * DMOD;
    float* yr = y + (size_t)n * DMOD;
    __shared__ float r1[256], r2[256];
    float s = 0.f, s2 = 0.f;
    for (int i = threadIdx.x; i < DMOD; i += 256) {
        float v = ar[i] + cr[i];
        s += v; s2 += v * v;
    }
    r1[threadIdx.x] = s; r2[threadIdx.x] = s2;
    __syncthreads();
    for (int st = 128; st > 0; st >>= 1) {
        if (threadIdx.x < st) {
            r1[threadIdx.x] += r1[threadIdx.x + st];
            r2[threadIdx.x] += r2[threadIdx.x + st];
        }
        __syncthreads();
    }
    const float mean = r1[0] * (1.f / DMOD);
    const float var = r2[0] * (1.f / DMOD) - mean * mean;
    const float rstd = rsqrtf(var + 1e-5f);
    for (int i = threadIdx.x; i < DMOD; i += 256) {
        float v = ar[i] + cr[i];
        yr[i] = (v - mean) * rstd * g[i] + b[i];
    }
}

// ---------------------------------------------------------------------------
extern "C" void kernel_launch(void* const* d_in, const int* in_sizes, int n_in,
                              void* d_out, int out_size)
{
    const float* x      = (const float*)d_in[0];
    const float* lgx    = (const float*)d_in[1];
    const int* in_deg   = (const int*)d_in[2];
    const int* out_deg  = (const int*)d_in[3];
    const int* dist     = (const int*)d_in[4];
    const int* pet      = (const int*)d_in[5];
    const float* paw    = (const float*)d_in[6];
    const float* rel_e  = (const float*)d_in[7];
    const float* rel_w  = (const float*)d_in[8];
    const float* ide    = (const float*)d_in[9];
    const float* ode    = (const float*)d_in[10];
    const float* plen   = (const float*)d_in[11];
    const float* Wq = (const float*)d_in[12];  const float* bq = (const float*)d_in[13];
    const float* Wk = (const float*)d_in[14];  const float* bk = (const float*)d_in[15];
    const float* Wv = (const float*)d_in[16];  const float* bv = (const float*)d_in[17];
    const float* Wo = (const float*)d_in[18];  const float* bo = (const float*)d_in[19];
    const float* ln1g = (const float*)d_in[20]; const float* ln1b = (const float*)d_in[21];
    const float* W1 = (const float*)d_in[22];  const float* b1 = (const float*)d_in[23];
    const float* W2 = (const float*)d_in[24];  const float* b2 = (const float*)d_in[25];
    const float* ln2g = (const float*)d_in[26]; const float* ln2b = (const float*)d_in[27];
    float* out = (float*)d_out;

    float *x2, *bias2d, *Wqkv, *bqkv, *qkv, *ao, *t, *h1, *ff, *part, *etw;
    cudaGetSymbolAddress((void**)&x2, g_x2);
    cudaGetSymbolAddress((void**)&bias2d, g_bias2d);
    cudaGetSymbolAddress((void**)&Wqkv, g_Wqkv);
    cudaGetSymbolAddress((void**)&bqkv, g_bqkv);
    cudaGetSymbolAddress((void**)&qkv, g_qkv);
    cudaGetSymbolAddress((void**)&ao, g_ao);
    cudaGetSymbolAddress((void**)&t, g_t);
    cudaGetSymbolAddress((void**)&h1, g_h1);
    cudaGetSymbolAddress((void**)&ff, g_ff);
    cudaGetSymbolAddress((void**)&part, g_part);
    cudaGetSymbolAddress((void**)&etw, g_etw);

    cudaFuncSetAttribute(tgemm_bat, cudaFuncAttributeMaxDynamicSharedMemorySize,
                         GSMEM_BYTES);
    cudaFuncSetAttribute(flash_k, cudaFuncAttributeMaxDynamicSharedMemorySize,
                         FLASH_SMEM);

    // side stream + events (host resources, created once; no device alloc)
    static cudaStream_t s2 = nullptr;
    static cudaEvent_t evFork = nullptr, evJoin = nullptr;
    if (!s2) {
        cudaStreamCreateWithFlags(&s2, cudaStreamNonBlocking);
        cudaEventCreateWithFlags(&evFork, cudaEventDisableTiming);
        cudaEventCreateWithFlags(&evJoin, cudaEventDisableTiming);
    }

    const size_t WB = (size_t)DMOD * DMOD * sizeof(float);
    const size_t ND = (size_t)NTOK * DMOD;

    // ---- fork: side stream does lgx copy + etw + bias2d ----
    cudaEventRecord(evFork, 0);
    cudaStreamWaitEvent(s2, evFork, 0);
    cudaMemcpyAsync(out + ND, lgx, (size_t)NTOK * 8 * DMOD * sizeof(float),
                    cudaMemcpyDeviceToDevice, s2);
    etw_k<<<1, 64, 0, s2>>>(rel_e, rel_w, etw);
    bias2d_k<<<(NTOK * NTOK) / 256, 256, 0, s2>>>(
        dist, (const int4*)pet, (const float4*)paw, plen, etw, bias2d);
    cudaEventRecord(evJoin, s2);

    // ---- main stream: weight pack + addemb + QKV ----
    cudaMemcpyAsync(Wqkv,            Wq, WB, cudaMemcpyDeviceToDevice);
    cudaMemcpyAsync(Wqkv + WB / 4,   Wk, WB, cudaMemcpyDeviceToDevice);
    cudaMemcpyAsync(Wqkv + WB / 2,   Wv, WB, cudaMemcpyDeviceToDevice);
    cudaMemcpyAsync(bqkv,            bq, DMOD * 4, cudaMemcpyDeviceToDevice);
    cudaMemcpyAsync(bqkv + DMOD,     bk, DMOD * 4, cudaMemcpyDeviceToDevice);
    cudaMemcpyAsync(bqkv + 2 * DMOD, bv, DMOD * 4, cudaMemcpyDeviceToDevice);

    addemb_k<<<NTOK, 256>>>(x, in_deg, out_deg, ide, ode, x2);

    float* q = qkv;
    float* k = qkv + ND;
    float* v = qkv + 2 * ND;

    // QKV split-K=2 over 3 batches -> partials, reduce(+bqkv)
    tgemm_bat<<<dim3(8, 16, 6), 256, GSMEM_BYTES>>>(
        x2, Wqkv, nullptr, part, NTOK, DMOD, DMOD,
        0, (size_t)DMOD * DMOD, ND, 0, 0, 2);
    reduceK_k<<<(int)(3 * ND / 4 / 256), 256>>>(
        (const float4*)part, (float4*)qkv, bqkv, 2, ND / 4, DMOD / 4, DMOD / 4);

    // ---- join: flash needs bias2d ----
    cudaStreamWaitEvent(0, evJoin, 0);
    flash_k<<<dim3(1, 16, HEADS), 256, FLASH_SMEM>>>(q, k, v, bias2d, ao);

    // output projection split-K=2 + reduce(+bo) + LN1
    tgemm_bat<<<dim3(8, 16, 2), 256, GSMEM_BYTES>>>(
        ao, Wo, nullptr, part, NTOK, DMOD, DMOD, 0, 0, ND, 0, 0, 2);
    reduceK_k<<<(int)(ND / 4 / 256), 256>>>(
        (const float4*)part, (float4*)t, bo, 2, ND / 4, DMOD / 4, 0);
    add_ln_k<<<NTOK, 256>>>(x2, t, ln1g, ln1b, h1);

    // FFN1 (+b1, relu)
    tgemm_bat<<<dim3(32, 16, 1), 256, GSMEM_BYTES>>>(
        h1, W1, b1, ff, NTOK, FFD, DMOD, 0, 0, 0, FFD, 1, 1);
    // FFN2 split-K=2 + reduce(+b2) + LN2
    tgemm_bat<<<dim3(8, 16, 2), 256, GSMEM_BYTES>>>(
        ff, W2, nullptr, part, NTOK, DMOD, FFD, 0, 0, ND, 0, 0, 2);
    reduceK_k<<<(int)(ND / 4 / 256), 256>>>(
        (const float4*)part, (float4*)t, b2, 2, ND / 4, DMOD / 4, 0);
    add_ln_k<<<NTOK, 256>>>(h1, t, ln2g, ln2b, out);
}